// round 14
// baseline (speedup 1.0000x reference)
#include <cuda_runtime.h>
#include <cuda_fp16.h>
#include <cstdint>
#include <cstddef>

// Problem constants
#define BV 4
#define HN 16
#define SV 1024
#define DV 64
#define BH (BV*HN)

// fp16 k operand (device scratch; no allocation)
__device__ __half g_khi[(size_t)BH * SV * DV];
// monotonic per-bh arrival counters (ticket scheme, graph-replay safe)
__device__ unsigned g_cnt[BH];

__device__ __forceinline__ uint32_t smem_u32(const void* p) {
    uint32_t a;
    asm("{ .reg .u64 t; cvta.to.shared.u64 t, %1; cvt.u32.u64 %0, t; }" : "=r"(a) : "l"(p));
    return a;
}
__device__ __forceinline__ uint32_t sw128(uint32_t off) {
    return off ^ ((off >> 3) & 0x70);
}
__device__ __forceinline__ void ldsm_x4(uint32_t addr, uint32_t& r0, uint32_t& r1,
                                        uint32_t& r2, uint32_t& r3) {
    asm volatile("ldmatrix.sync.aligned.m8n8.x4.shared.b16 {%0,%1,%2,%3}, [%4];"
                 : "=r"(r0), "=r"(r1), "=r"(r2), "=r"(r3) : "r"(addr));
}
__device__ __forceinline__ void mma_f16(float* c, const uint32_t* a,
                                        uint32_t b0, uint32_t b1) {
    asm volatile(
        "mma.sync.aligned.m16n8k16.row.col.f32.f16.f16.f32 "
        "{%0,%1,%2,%3}, {%4,%5,%6,%7}, {%8,%9}, {%0,%1,%2,%3};"
        : "+f"(c[0]), "+f"(c[1]), "+f"(c[2]), "+f"(c[3])
        : "r"(a[0]), "r"(a[1]), "r"(a[2]), "r"(a[3]), "r"(b0), "r"(b1));
}
__device__ __forceinline__ void cp_async16(uint32_t smem_dst, const void* gsrc) {
    asm volatile("cp.async.cg.shared.global [%0], [%1], 16;"
                 :: "r"(smem_dst), "l"(gsrc));
}
#define CP_COMMIT() asm volatile("cp.async.commit_group;" ::: "memory")
#define CP_WAIT0()  asm volatile("cp.async.wait_group 0;"  ::: "memory")

// ---------------------------------------------------------------------------
// Single fused kernel (see R13), j-loop unrolled, 2-stage shuffle-widened
// epilogue: every STG.128 covers 4 rows x 128B (full wavefronts).
// grid (1, 16, 64) = 1024 CTAs, 128 threads, 4 CTAs/SM.
// ---------------------------------------------------------------------------
#define OFF_QH 0
#define OFF_QL 8192
#define OFF_MH 16384
#define OFF_ML 24576
#define OFF_A  16384
#define OFF_B0 32768
#define OFF_B1 0
#define SC_SMEM (49152 + 1024)

__global__ __launch_bounds__(128, 4)
void score_mma_kernel(const float* __restrict__ q,
                      const float* __restrict__ kf,
                      const float* __restrict__ W,
                      const float* __restrict__ b,
                      const float* __restrict__ Wd,
                      float* __restrict__ out)
{
    extern __shared__ char smem_raw[];
    const uint32_t smem_base = smem_u32(smem_raw);
    const uint32_t base_al   = (smem_base + 1023u) & ~1023u;
    char* tilec = smem_raw + (base_al - smem_base);

    const int t    = threadIdx.x;
    const int wid  = t >> 5;
    const int lane = t & 31;
    const int bh   = blockIdx.z;
    const int h    = bh % HN;
    const int i0   = blockIdx.y * 64;

    const size_t boff = (size_t)bh * SV * DV;
    const __half* kh = g_khi + boff;

    // ================= K-SLICE CONVERT (own 64 rows) =================
    {
        const float* ks = kf + boff + (size_t)i0 * DV;
        __half2* kd = reinterpret_cast<__half2*>(g_khi + boff + (size_t)i0 * DV);
        #pragma unroll
        for (int it = 0; it < 8; it++) {
            const int idx = t + it * 128;
            float4 v = reinterpret_cast<const float4*>(ks)[idx];
            kd[2 * idx]     = __floats2half2_rn(v.x, v.y);
            kd[2 * idx + 1] = __floats2half2_rn(v.z, v.w);
        }
    }
    __threadfence();
    __syncthreads();
    unsigned target = 0;
    if (t == 0) {
        unsigned my = atomicAdd(&g_cnt[bh], 1u);
        target = (my / 16u + 1u) * 16u;
    }

    // =========================== FOLD PROLOGUE ===========================
    {
        const float* qb = q + boff + (size_t)i0 * DV;
        const float* Wh = W + (size_t)h * DV * DV;
        const float  wd = Wd[h];

        #pragma unroll
        for (int it = 0; it < 32; it++) {
            const int idx = t + it * 128;          // d*64+e
            const int d = idx >> 6, e = idx & 63;
            float val = wd * Wh[idx] + (d == e ? 32.0f : 0.0f);
            __half hi = __float2half(val);
            __half lo = __float2half(val - __half2float(hi));
            const uint32_t off = sw128((uint32_t)(e * 128 + d * 2));
            *reinterpret_cast<__half*>(tilec + OFF_MH + off) = hi;
            *reinterpret_cast<__half*>(tilec + OFF_ML + off) = lo;
        }

        #pragma unroll
        for (int it = 0; it < 4; it++) {
            const int idx = t + it * 128;          // 0..511
            const float4 v0 = reinterpret_cast<const float4*>(qb)[idx * 2];
            const float4 v1 = reinterpret_cast<const float4*>(qb)[idx * 2 + 1];
            __half h0 = __float2half(v0.x), h1 = __float2half(v0.y);
            __half h2 = __float2half(v0.z), h3 = __float2half(v0.w);
            __half h4 = __float2half(v1.x), h5 = __float2half(v1.y);
            __half h6 = __float2half(v1.z), h7 = __float2half(v1.w);
            __half2 hv[4] = { __half2(h0,h1), __half2(h2,h3), __half2(h4,h5), __half2(h6,h7) };
            __half2 lv[4] = {
                __floats2half2_rn(v0.x - __half2float(h0), v0.y - __half2float(h1)),
                __floats2half2_rn(v0.z - __half2float(h2), v0.w - __half2float(h3)),
                __floats2half2_rn(v1.x - __half2float(h4), v1.y - __half2float(h5)),
                __floats2half2_rn(v1.z - __half2float(h6), v1.w - __half2float(h7)) };
            const uint32_t off = sw128((uint32_t)idx * 16);
            *reinterpret_cast<uint4*>(tilec + OFF_QH + off) = *reinterpret_cast<uint4*>(hv);
            *reinterpret_cast<uint4*>(tilec + OFF_QL + off) = *reinterpret_cast<uint4*>(lv);
        }
        __syncthreads();

        const int m0w = (wid & 1) * 32;
        const int n0w = (wid >> 1) * 32;

        float acc[2][4][4];
        #pragma unroll
        for (int m = 0; m < 2; m++)
            #pragma unroll
            for (int n = 0; n < 4; n++)
                #pragma unroll
                for (int r = 0; r < 4; r++) acc[m][n][r] = 0.0f;

        const uint32_t a_row = lane & 15;
        const uint32_t a_ch  = (lane >> 4) << 4;
        const uint32_t b_row = (lane & 7) | ((lane >> 4) << 3);
        const uint32_t b_ch  = ((lane >> 3) & 1) << 4;

        #pragma unroll
        for (int kk = 0; kk < 4; kk++) {
            const uint32_t kb = (uint32_t)kk * 32;
            uint32_t ah[2][4], al[2][4];
            #pragma unroll
            for (int m = 0; m < 2; m++) {
                const uint32_t ro = sw128((uint32_t)(m0w + m * 16 + a_row) * 128 + kb + a_ch);
                ldsm_x4(base_al + OFF_QH + ro, ah[m][0], ah[m][1], ah[m][2], ah[m][3]);
                ldsm_x4(base_al + OFF_QL + ro, al[m][0], al[m][1], al[m][2], al[m][3]);
            }
            uint32_t bh_f[4][2], bl_f[4][2];
            #pragma unroll
            for (int tn = 0; tn < 2; tn++) {
                const uint32_t ro = sw128((uint32_t)(n0w + tn * 16 + b_row) * 128 + kb + b_ch);
                ldsm_x4(base_al + OFF_MH + ro, bh_f[2*tn][0], bh_f[2*tn][1], bh_f[2*tn+1][0], bh_f[2*tn+1][1]);
                ldsm_x4(base_al + OFF_ML + ro, bl_f[2*tn][0], bl_f[2*tn][1], bl_f[2*tn+1][0], bl_f[2*tn+1][1]);
            }
            #pragma unroll
            for (int m = 0; m < 2; m++)
                #pragma unroll
                for (int n = 0; n < 4; n++) {
                    mma_f16(acc[m][n], ah[m], bh_f[n][0], bh_f[n][1]);
                    mma_f16(acc[m][n], ah[m], bl_f[n][0], bl_f[n][1]);
                    mma_f16(acc[m][n], al[m], bh_f[n][0], bh_f[n][1]);
                }
        }
        __syncthreads();

        #pragma unroll
        for (int m = 0; m < 2; m++) {
            #pragma unroll
            for (int half = 0; half < 2; half++) {
                const int row = m0w + m * 16 + half * 8 + (lane >> 2);
                #pragma unroll
                for (int n = 0; n < 4; n++) {
                    const int col = n0w + n * 8 + (lane & 3) * 2;
                    __half2 v = __floats2half2_rn(acc[m][n][half * 2], acc[m][n][half * 2 + 1]);
                    const uint32_t off = sw128((uint32_t)(row * 128 + col * 2));
                    *reinterpret_cast<__half2*>(tilec + OFF_A + off) = v;
                }
            }
        }
    }

    // ================= TICKET BARRIER: wait for all 16 peers =================
    if (t == 0) {
        while (atomicAdd(&g_cnt[bh], 0u) < target) __nanosleep(64);
        __threadfence();
    }
    __syncthreads();

    // ---- Prefetch B tile 0 ----
    #pragma unroll
    for (int it = 0; it < 8; it++) {
        const int idx = t + it * 128;
        cp_async16(base_al + OFF_B0 + sw128((uint32_t)idx * 16), kh + (size_t)idx * 8);
    }
    CP_COMMIT();
    CP_WAIT0();
    __syncthreads();

    // ============================ J-LOOP ============================
    const int m0wj = (wid & 1) * 32;
    const int n0wj = (wid >> 1) * 64;

    const uint32_t a_row = lane & 15;
    const uint32_t a_ch  = (lane >> 4) << 4;
    const uint32_t b_row = (lane & 7) | ((lane >> 4) << 3);
    const uint32_t b_ch  = ((lane >> 3) & 1) << 4;

    const float cbias = Wd[h] * b[h];
    float* obase = out + (size_t)bh * SV * SV;

    const int l3   = lane & 3;
    const int sel  = l3 & 1;              // stage-1 parity
    const int coff = (l3 >> 1) * 4;       // stage-1 col sub-offset
    const int c0   = sel * 8 + coff;      // col within 16-col group: 0,8,4,12
    const int bit2 = (lane >> 2) & 1;     // row LSB within pair
    const int a8   = lane >> 3;           // row-pair index 0..3

    #pragma unroll
    for (int jt = 0; jt < 8; jt++) {
        const uint32_t Bb = base_al + ((jt & 1) ? OFF_B1 : OFF_B0);

        if (jt < 7) {
            const __half* kn = kh + (size_t)(jt + 1) * 128 * DV;
            const uint32_t Bn = base_al + ((jt & 1) ? OFF_B0 : OFF_B1);
            #pragma unroll
            for (int it = 0; it < 8; it++) {
                const int idx = t + it * 128;
                cp_async16(Bn + sw128((uint32_t)idx * 16), kn + (size_t)idx * 8);
            }
            CP_COMMIT();
        }

        // ---- compute 64x128 tile (warp tile 32x64) ----
        float acc[2][8][4];
        #pragma unroll
        for (int m = 0; m < 2; m++)
            #pragma unroll
            for (int n = 0; n < 8; n++)
                #pragma unroll
                for (int r = 0; r < 4; r++) acc[m][n][r] = 0.0f;

        #pragma unroll
        for (int kk = 0; kk < 4; kk++) {
            const uint32_t kb = (uint32_t)kk * 32;
            uint32_t a[2][4];
            #pragma unroll
            for (int m = 0; m < 2; m++) {
                const uint32_t ro = sw128((uint32_t)(m0wj + m * 16 + a_row) * 128 + kb + a_ch);
                ldsm_x4(base_al + OFF_A + ro, a[m][0], a[m][1], a[m][2], a[m][3]);
            }
            uint32_t bf[8][2];
            #pragma unroll
            for (int tn = 0; tn < 4; tn++) {
                const uint32_t ro = sw128((uint32_t)(n0wj + tn * 16 + b_row) * 128 + kb + b_ch);
                ldsm_x4(Bb + ro, bf[2*tn][0], bf[2*tn][1], bf[2*tn+1][0], bf[2*tn+1][1]);
            }
            #pragma unroll
            for (int m = 0; m < 2; m++)
                #pragma unroll
                for (int n = 0; n < 8; n++)
                    mma_f16(acc[m][n], a[m], bf[n][0], bf[n][1]);
        }

        // ---- 2-stage shuffle-widened epilogue: 4 rows x 128B per STG ----
        #pragma unroll
        for (int m = 0; m < 2; m++) {
            #pragma unroll
            for (int half = 0; half < 2; half++) {
                // Stage 1 (xor 1): assemble V[i2] = float4 at (own row, cols 16*i2 + c0)
                float4 V[4];
                #pragma unroll
                for (int i2 = 0; i2 < 4; i2++) {
                    const float e0 = acc[m][2*i2][half*2+0] + cbias;
                    const float e1 = acc[m][2*i2][half*2+1] + cbias;
                    const float o0 = acc[m][2*i2+1][half*2+0] + cbias;
                    const float o1 = acc[m][2*i2+1][half*2+1] + cbias;
                    const float cx = sel ? e0 : o0;
                    const float cy = sel ? e1 : o1;
                    const float ax = sel ? o0 : e0;
                    const float ay = sel ? o1 : e1;
                    const float rx = __shfl_xor_sync(0xffffffffu, cx, 1);
                    const float ry = __shfl_xor_sync(0xffffffffu, cy, 1);
                    V[i2].x = sel ? rx : ax;
                    V[i2].y = sel ? ry : ay;
                    V[i2].z = sel ? ax : rx;
                    V[i2].w = sel ? ay : ry;
                }
                // Stage 2 (xor 4): swap odd-i2 fragments across the row pair
                #pragma unroll
                for (int d = 0; d < 2; d++) {
                    V[2*d+1].x = __shfl_xor_sync(0xffffffffu, V[2*d+1].x, 4);
                    V[2*d+1].y = __shfl_xor_sync(0xffffffffu, V[2*d+1].y, 4);
                    V[2*d+1].z = __shfl_xor_sync(0xffffffffu, V[2*d+1].z, 4);
                    V[2*d+1].w = __shfl_xor_sync(0xffffffffu, V[2*d+1].w, 4);
                }
                // Stores: instr (g,d) covers rows 2*a8+g (4 rows) x 128B
                const int rbase = i0 + m0wj + m * 16 + half * 8 + 2 * a8;
                #pragma unroll
                for (int g = 0; g < 2; g++) {
                    float* prow = obase + (size_t)(rbase + g) * SV + jt * 128 + n0wj;
                    const int swp = bit2 ^ g;
                    #pragma unroll
                    for (int d = 0; d < 2; d++) {
                        const float4 val = swp ? V[2*d+1] : V[2*d];
                        const int col = 32 * d + 16 * swp + c0;
                        asm volatile("st.global.cs.v4.f32 [%0], {%1,%2,%3,%4};"
                                     :: "l"(prow + col),
                                        "f"(val.x), "f"(val.y), "f"(val.z), "f"(val.w)
                                     : "memory");
                    }
                }
            }
        }

        if (jt < 7) {
            CP_WAIT0();
            __syncthreads();
        }
    }
}

// ---------------------------------------------------------------------------
extern "C" void kernel_launch(void* const* d_in, const int* in_sizes, int n_in,
                              void* d_out, int out_size)
{
    const float* q  = (const float*)d_in[0];
    const float* k  = (const float*)d_in[1];
    const float* W  = (const float*)d_in[2];
    const float* b  = (const float*)d_in[3];
    const float* Wd = (const float*)d_in[4];
    float* out = (float*)d_out;

    cudaFuncSetAttribute(score_mma_kernel,
                         cudaFuncAttributeMaxDynamicSharedMemorySize, SC_SMEM);

    dim3 g3(1, SV / 64, BH);
    score_mma_kernel<<<g3, 128, SC_SMEM>>>(q, k, W, b, Wd, out);
}